// round 4
// baseline (speedup 1.0000x reference)
#include <cuda_runtime.h>

#define BIGV 1e10f
#define TT 1024
#define BB 32
#define DD 64
#define NDIAG 2047   // row+col in [0, 2046]

// Diagonal-major cost scratch: g_cost[b][d][row], d = row+col.
// 32 * 2047 * 1024 floats = 268 MB (static __device__ scratch, sanctioned).
static __device__ float g_cost[(size_t)BB * NDIAG * TT];

// ---------------------------------------------------------------------------
// Kernel A: cost matrix, 64x64 tiles, 4x4 register tiling, K=64 fully in smem.
// Writes results in anti-diagonal-major layout so the DP kernel reads coalesced.
// ---------------------------------------------------------------------------
__global__ __launch_bounds__(256) void cost_kernel(const float* __restrict__ x,
                                                   const float* __restrict__ y) {
    const int bz = blockIdx.z;   // batch
    const int br = blockIdx.y;   // row tile (16)
    const int bc = blockIdx.x;   // col tile (16)
    const int tid = threadIdx.x; // 256 threads

    __shared__ float arena[2 * 64 * 65];          // 33.3 KB
    __shared__ float x2s[64], y2s[64];
    float* xsT = arena;                           // xsT[k*65 + r]
    float* ysT = arena + 64 * 65;                 // ysT[k*65 + c]
    float (*res)[72] = (float (*)[72])arena;      // res[64][72] aliases arena

    const float* xb = x + ((size_t)bz * TT + br * 64) * DD;
    const float* yb = y + ((size_t)bz * TT + bc * 64) * DD;

    #pragma unroll
    for (int i = 0; i < 16; i++) {
        int idx = tid + i * 256;   // 0..4095
        int r = idx >> 6;
        int d = idx & 63;
        xsT[d * 65 + r] = xb[r * DD + d];
        ysT[d * 65 + r] = yb[r * DD + d];
    }
    __syncthreads();

    if (tid < 64) {
        float s = 0.f;
        #pragma unroll
        for (int k = 0; k < 64; k++) { float v = xsT[k * 65 + tid]; s = fmaf(v, v, s); }
        x2s[tid] = s;
    } else if (tid < 128) {
        int c = tid - 64;
        float s = 0.f;
        #pragma unroll
        for (int k = 0; k < 64; k++) { float v = ysT[k * 65 + c]; s = fmaf(v, v, s); }
        y2s[c] = s;
    }

    const int tx = tid & 15;   // col group
    const int ty = tid >> 4;   // row group
    float acc[4][4] = {};
    #pragma unroll
    for (int k = 0; k < 64; k++) {
        float xr[4], yc[4];
        #pragma unroll
        for (int r = 0; r < 4; r++) xr[r] = xsT[k * 65 + ty * 4 + r];
        #pragma unroll
        for (int c = 0; c < 4; c++) yc[c] = ysT[k * 65 + tx * 4 + c];
        #pragma unroll
        for (int r = 0; r < 4; r++)
            #pragma unroll
            for (int c = 0; c < 4; c++)
                acc[r][c] = fmaf(xr[r], yc[c], acc[r][c]);
    }
    __syncthreads();

    float xr2[4], yc2[4];
    #pragma unroll
    for (int r = 0; r < 4; r++) xr2[r] = x2s[ty * 4 + r];
    #pragma unroll
    for (int c = 0; c < 4; c++) yc2[c] = y2s[tx * 4 + c];
    #pragma unroll
    for (int r = 0; r < 4; r++)
        #pragma unroll
        for (int c = 0; c < 4; c++)
            res[ty * 4 + r][tx * 4 + c] =
                fmaxf(xr2[r] + yc2[c] - 2.0f * acc[r][c], 0.0f);
    __syncthreads();

    const int wid = tid >> 5, lane = tid & 31;
    const int dbase = br * 64 + bc * 64;
    for (int dl = wid; dl < 127; dl += 8) {
        int rlo = dl > 63 ? dl - 63 : 0;
        int rhi = dl < 63 ? dl : 63;
        size_t gbase = ((size_t)bz * NDIAG + (dbase + dl)) * TT + (size_t)br * 64;
        for (int r0 = rlo; r0 <= rhi; r0 += 32) {
            int r = r0 + lane;
            if (r <= rhi) g_cost[gbase + r] = res[r][dl - r];
        }
    }
}

// ---------------------------------------------------------------------------
// Kernel B: anti-diagonal DP, register-resident, 2 rows/thread, 512 thr/CTA
// (16 warps = 4/SMSP for latency hiding; round-3's 2/SMSP starved the issue
// pipe at 19% IPC). DP state in registers; left halo via shfl within warp +
// smem across warps; one __syncthreads per diagonal; depth-3 float2 prefetch
// ring on the cost loads. softmin via exp(0)=1 identity (3 MUFU/cell).
// ---------------------------------------------------------------------------
__global__ __launch_bounds__(512) void dp_kernel(float* __restrict__ out) {
    const int b = blockIdx.x;
    const int t = threadIdx.x;        // 0..511
    const int lane = t & 31;
    const int w = t >> 5;             // warp 0..15
    const int r0 = t << 1;            // first owned row (2 rows: r0, r0+1)

    __shared__ float halo[2][16];

    // v1[j] = d_{k-1}[r0+j+1], v2[j] = d_{k-2}[r0+j+1]
    float v1[2], v2[2];
    v1[0] = v1[1] = BIGV;
    v2[0] = v2[1] = BIGV;
    float L1 = BIGV;                     // d_{k-1}[r0]
    float L2 = (t == 0) ? 0.0f : BIGV;   // d_{k-2}[r0]   (d0[0] = 0)

    const float* costbase = g_cost + (size_t)b * NDIAG * TT + r0;

    // Thread has valid cells on diag k iff k in [kminA, kmaxA].
    const int kminA = r0 + 2;            // row r0 first valid
    const int kmaxA = r0 + 2 + TT;       // row r0+1 last valid (r0+1+2+TT-1)

    // Prefetch ring: pf0 -> diag k, pf1 -> k+1, pf2 -> k+2 (plane k-2).
    float2 pf0 = make_float2(0, 0), pf1 = pf0, pf2 = pf0;
    if (2 >= kminA) pf0 = *(const float2*)(costbase);
    if (3 >= kminA) pf1 = *(const float2*)(costbase + (size_t)1 * TT);
    if (4 >= kminA) pf2 = *(const float2*)(costbase + (size_t)2 * TT);

    float res = BIGV;

    #pragma unroll 3
    for (int k = 2; k <= 2 * TT; k++) {
        float2 cost = pf0;
        pf0 = pf1; pf1 = pf2;
        const int kd = k + 3;
        if ((kd <= 2 * TT) & (kd >= kminA) & (kd <= kmaxA))
            pf2 = *(const float2*)(costbase + (size_t)(kd - 2) * TT);

        // valid rows on diagonal k: r in [k-1-T, k-2]
        const int rlo = k - 1 - TT;
        const int rhi = k - 2;

        float cur0, cur1;
        if ((k >= kminA) & (k <= kmaxA)) {
            // j=1 first: it feeds the shfl/halo, shortens the serial chain.
            {
                float a  = v2[0];
                float bb = v1[0];
                float c  = v1[1];
                float mnab = fminf(a, bb);
                float mxab = fmaxf(a, bb);
                float mn   = fminf(mnab, c);
                float hi   = fmaxf(mxab, c);
                float mid  = fmaxf(mnab, fminf(mxab, c));
                float s  = 1.0f + __expf(mn - mid) + __expf(mn - hi);
                float sm = mn - __logf(s);
                int r = r0 + 1;
                cur1 = ((r >= rlo) & (r <= rhi)) ? cost.y + sm : BIGV;
            }
            {
                float a  = L2;
                float bb = L1;
                float c  = v1[0];
                float mnab = fminf(a, bb);
                float mxab = fmaxf(a, bb);
                float mn   = fminf(mnab, c);
                float hi   = fmaxf(mxab, c);
                float mid  = fmaxf(mnab, fminf(mxab, c));
                float s  = 1.0f + __expf(mn - mid) + __expf(mn - hi);
                float sm = mn - __logf(s);
                cur0 = ((r0 >= rlo) & (r0 <= rhi)) ? cost.x + sm : BIGV;
            }
            res = cur1;
        } else {
            cur0 = BIGV; cur1 = BIGV;
        }

        // halo exchange: new d_k[r0] is left neighbor thread's cur1
        float nb = __shfl_up_sync(0xffffffffu, cur1, 1);
        if (lane == 31) halo[k & 1][w] = cur1;
        __syncthreads();
        if (lane == 0) nb = (w == 0) ? BIGV : halo[k & 1][w - 1];

        L2 = L1;
        L1 = nb;
        v2[0] = v1[0]; v2[1] = v1[1];
        v1[0] = cur0;  v1[1] = cur1;
    }

    // answer = d_{2T}[T] : DP idx 1024 -> r0+2 = 1024 -> thread 511, j=1 (k=2048)
    if (t == 511) out[b] = res;
}

extern "C" void kernel_launch(void* const* d_in, const int* in_sizes, int n_in,
                              void* d_out, int out_size) {
    const float* x = (const float*)d_in[0];
    const float* y = (const float*)d_in[1];
    float* out = (float*)d_out;

    dim3 gridA(TT / 64, TT / 64, BB);   // (16, 16, 32)
    cost_kernel<<<gridA, 256>>>(x, y);
    dp_kernel<<<BB, 512>>>(out);
}

// round 5
// speedup vs baseline: 1.0638x; 1.0638x over previous
#include <cuda_runtime.h>

#define BIGV 1e10f
#define TT 1024
#define BB 32
#define DD 64
#define NDIAG 2047   // row+col in [0, 2046]

// Diagonal-major cost scratch: g_cost[b][d][row], d = row+col.
// 32 * 2047 * 1024 floats = 268 MB (static __device__ scratch, sanctioned).
static __device__ float g_cost[(size_t)BB * NDIAG * TT];

// ---------------------------------------------------------------------------
// Kernel A: cost matrix, 64x64 tiles, 4x4 register tiling, K=64 fully in smem.
// Writes results in anti-diagonal-major layout so the DP kernel reads coalesced.
// (unchanged from round 1 — ~195us, attacked next round)
// ---------------------------------------------------------------------------
__global__ __launch_bounds__(256) void cost_kernel(const float* __restrict__ x,
                                                   const float* __restrict__ y) {
    const int bz = blockIdx.z;   // batch
    const int br = blockIdx.y;   // row tile (16)
    const int bc = blockIdx.x;   // col tile (16)
    const int tid = threadIdx.x; // 256 threads

    __shared__ float arena[2 * 64 * 65];          // 33.3 KB
    __shared__ float x2s[64], y2s[64];
    float* xsT = arena;                           // xsT[k*65 + r]
    float* ysT = arena + 64 * 65;                 // ysT[k*65 + c]
    float (*res)[72] = (float (*)[72])arena;      // res[64][72] aliases arena

    const float* xb = x + ((size_t)bz * TT + br * 64) * DD;
    const float* yb = y + ((size_t)bz * TT + bc * 64) * DD;

    #pragma unroll
    for (int i = 0; i < 16; i++) {
        int idx = tid + i * 256;   // 0..4095
        int r = idx >> 6;
        int d = idx & 63;
        xsT[d * 65 + r] = xb[r * DD + d];
        ysT[d * 65 + r] = yb[r * DD + d];
    }
    __syncthreads();

    if (tid < 64) {
        float s = 0.f;
        #pragma unroll
        for (int k = 0; k < 64; k++) { float v = xsT[k * 65 + tid]; s = fmaf(v, v, s); }
        x2s[tid] = s;
    } else if (tid < 128) {
        int c = tid - 64;
        float s = 0.f;
        #pragma unroll
        for (int k = 0; k < 64; k++) { float v = ysT[k * 65 + c]; s = fmaf(v, v, s); }
        y2s[c] = s;
    }

    const int tx = tid & 15;   // col group
    const int ty = tid >> 4;   // row group
    float acc[4][4] = {};
    #pragma unroll
    for (int k = 0; k < 64; k++) {
        float xr[4], yc[4];
        #pragma unroll
        for (int r = 0; r < 4; r++) xr[r] = xsT[k * 65 + ty * 4 + r];
        #pragma unroll
        for (int c = 0; c < 4; c++) yc[c] = ysT[k * 65 + tx * 4 + c];
        #pragma unroll
        for (int r = 0; r < 4; r++)
            #pragma unroll
            for (int c = 0; c < 4; c++)
                acc[r][c] = fmaf(xr[r], yc[c], acc[r][c]);
    }
    __syncthreads();

    float xr2[4], yc2[4];
    #pragma unroll
    for (int r = 0; r < 4; r++) xr2[r] = x2s[ty * 4 + r];
    #pragma unroll
    for (int c = 0; c < 4; c++) yc2[c] = y2s[tx * 4 + c];
    #pragma unroll
    for (int r = 0; r < 4; r++)
        #pragma unroll
        for (int c = 0; c < 4; c++)
            res[ty * 4 + r][tx * 4 + c] =
                fmaxf(xr2[r] + yc2[c] - 2.0f * acc[r][c], 0.0f);
    __syncthreads();

    const int wid = tid >> 5, lane = tid & 31;
    const int dbase = br * 64 + bc * 64;
    for (int dl = wid; dl < 127; dl += 8) {
        int rlo = dl > 63 ? dl - 63 : 0;
        int rhi = dl < 63 ? dl : 63;
        size_t gbase = ((size_t)bz * NDIAG + (dbase + dl)) * TT + (size_t)br * 64;
        for (int r0 = rlo; r0 <= rhi; r0 += 32) {
            int r = r0 + lane;
            if (r <= rhi) g_cost[gbase + r] = res[r][dl - r];
        }
    }
}

__device__ __forceinline__ void bar_named(int id, int cnt) {
    asm volatile("bar.sync %0, %1;" :: "r"(id), "r"(cnt) : "memory");
}

// ---------------------------------------------------------------------------
// Kernel B: anti-diagonal DP, register-resident, 2 rows/thread, 512 thr/CTA.
// NO global barrier: warp w rendezvous only with its neighbors via named
// pair-barriers (id w pairs warps w,w+1; 64 threads each). Arrival order is
// left-pair (id w-1) then right-pair (id w) — monotone in id, deadlock-free.
// Double-buffered halo + the pair rendezvous gives read-before-overwrite.
// Warps drift into a skew gradient; per-iteration jitter averages instead of
// maxing across 16 warps (the round-4 lockstep cost).
// ---------------------------------------------------------------------------
__global__ __launch_bounds__(512) void dp_kernel(float* __restrict__ out) {
    const int b = blockIdx.x;
    const int t = threadIdx.x;        // 0..511
    const int lane = t & 31;
    const int w = t >> 5;             // warp 0..15
    const int r0 = t << 1;            // first owned row (2 rows: r0, r0+1)

    __shared__ float halo[2][16];

    // v1[j] = d_{k-1}[r0+j+1], v2[j] = d_{k-2}[r0+j+1]
    float v1[2], v2[2];
    v1[0] = v1[1] = BIGV;
    v2[0] = v2[1] = BIGV;
    float L1 = BIGV;                     // d_{k-1}[r0]
    float L2 = (t == 0) ? 0.0f : BIGV;   // d_{k-2}[r0]   (d0[0] = 0)

    const float* costbase = g_cost + (size_t)b * NDIAG * TT + r0;

    // Thread has valid cells on diag k iff k in [kminA, kmaxA].
    const int kminA = r0 + 2;            // row r0 first valid
    const int kmaxA = r0 + 2 + TT;       // row r0+1 last valid

    // Prefetch ring: pf0 -> diag k, pf1 -> k+1, pf2 -> k+2 (plane k-2).
    float2 pf0 = make_float2(0, 0), pf1 = pf0, pf2 = pf0;
    if (2 >= kminA) pf0 = *(const float2*)(costbase);
    if (3 >= kminA) pf1 = *(const float2*)(costbase + (size_t)1 * TT);
    if (4 >= kminA) pf2 = *(const float2*)(costbase + (size_t)2 * TT);

    float res = BIGV;

    #pragma unroll 3
    for (int k = 2; k <= 2 * TT; k++) {
        float2 cost = pf0;
        pf0 = pf1; pf1 = pf2;
        const int kd = k + 3;
        if ((kd <= 2 * TT) & (kd >= kminA) & (kd <= kmaxA))
            pf2 = *(const float2*)(costbase + (size_t)(kd - 2) * TT);

        // valid rows on diagonal k: r in [k-1-T, k-2]
        const int rlo = k - 1 - TT;
        const int rhi = k - 2;

        float cur0, cur1;
        if ((k >= kminA) & (k <= kmaxA)) {
            // j=1 first: it feeds the shfl/halo, shortens the serial chain.
            {
                float a  = v2[0];
                float bb = v1[0];
                float c  = v1[1];
                float mnab = fminf(a, bb);
                float mxab = fmaxf(a, bb);
                float mn   = fminf(mnab, c);
                float hi   = fmaxf(mxab, c);
                float mid  = fmaxf(mnab, fminf(mxab, c));
                float s  = 1.0f + __expf(mn - mid) + __expf(mn - hi);
                float sm = mn - __logf(s);
                int r = r0 + 1;
                cur1 = ((r >= rlo) & (r <= rhi)) ? cost.y + sm : BIGV;
            }
            {
                float a  = L2;
                float bb = L1;
                float c  = v1[0];
                float mnab = fminf(a, bb);
                float mxab = fmaxf(a, bb);
                float mn   = fminf(mnab, c);
                float hi   = fmaxf(mxab, c);
                float mid  = fmaxf(mnab, fminf(mxab, c));
                float s  = 1.0f + __expf(mn - mid) + __expf(mn - hi);
                float sm = mn - __logf(s);
                cur0 = ((r0 >= rlo) & (r0 <= rhi)) ? cost.x + sm : BIGV;
            }
            res = cur1;
        } else {
            cur0 = BIGV; cur1 = BIGV;
        }

        // halo handoff: new d_k[r0] is left neighbor thread's cur1
        float nb = __shfl_up_sync(0xffffffffu, cur1, 1);
        if (lane == 31) halo[k & 1][w] = cur1;

        // neighbor-only rendezvous (replaces __syncthreads):
        //   id w-1 with left neighbor (its write now visible),
        //   id w   with right neighbor (it has read our k-2 value).
        if (w > 0)  bar_named(w - 1, 64);
        if (w < 15) bar_named(w, 64);

        if (lane == 0) nb = (w == 0) ? BIGV : halo[k & 1][w - 1];

        L2 = L1;
        L1 = nb;
        v2[0] = v1[0]; v2[1] = v1[1];
        v1[0] = cur0;  v1[1] = cur1;
    }

    // answer = d_{2T}[T] : DP idx 1024 -> thread 511, j=1 (k = 2048)
    if (t == 511) out[b] = res;
}

extern "C" void kernel_launch(void* const* d_in, const int* in_sizes, int n_in,
                              void* d_out, int out_size) {
    const float* x = (const float*)d_in[0];
    const float* y = (const float*)d_in[1];
    float* out = (float*)d_out;

    dim3 gridA(TT / 64, TT / 64, BB);   // (16, 16, 32)
    cost_kernel<<<gridA, 256>>>(x, y);
    dp_kernel<<<BB, 512>>>(out);
}

// round 6
// speedup vs baseline: 1.4226x; 1.3374x over previous
#include <cuda_runtime.h>

#define BIGV 1e10f
#define TT 1024
#define BB 32
#define DD 64
#define NDIAG 2047   // row+col in [0, 2046]

// Diagonal-major cost scratch: g_cost[b][d][row], d = row+col.
// 32 * 2047 * 1024 floats = 268 MB (static __device__ scratch, sanctioned).
static __device__ float g_cost[(size_t)BB * NDIAG * TT];

// ---------------------------------------------------------------------------
// Kernel A: cost matrix (unchanged; ~attacked next round).
// ---------------------------------------------------------------------------
__global__ __launch_bounds__(256) void cost_kernel(const float* __restrict__ x,
                                                   const float* __restrict__ y) {
    const int bz = blockIdx.z;   // batch
    const int br = blockIdx.y;   // row tile (16)
    const int bc = blockIdx.x;   // col tile (16)
    const int tid = threadIdx.x; // 256 threads

    __shared__ float arena[2 * 64 * 65];          // 33.3 KB
    __shared__ float x2s[64], y2s[64];
    float* xsT = arena;                           // xsT[k*65 + r]
    float* ysT = arena + 64 * 65;                 // ysT[k*65 + c]
    float (*res)[72] = (float (*)[72])arena;      // res[64][72] aliases arena

    const float* xb = x + ((size_t)bz * TT + br * 64) * DD;
    const float* yb = y + ((size_t)bz * TT + bc * 64) * DD;

    #pragma unroll
    for (int i = 0; i < 16; i++) {
        int idx = tid + i * 256;   // 0..4095
        int r = idx >> 6;
        int d = idx & 63;
        xsT[d * 65 + r] = xb[r * DD + d];
        ysT[d * 65 + r] = yb[r * DD + d];
    }
    __syncthreads();

    if (tid < 64) {
        float s = 0.f;
        #pragma unroll
        for (int k = 0; k < 64; k++) { float v = xsT[k * 65 + tid]; s = fmaf(v, v, s); }
        x2s[tid] = s;
    } else if (tid < 128) {
        int c = tid - 64;
        float s = 0.f;
        #pragma unroll
        for (int k = 0; k < 64; k++) { float v = ysT[k * 65 + c]; s = fmaf(v, v, s); }
        y2s[c] = s;
    }

    const int tx = tid & 15;   // col group
    const int ty = tid >> 4;   // row group
    float acc[4][4] = {};
    #pragma unroll
    for (int k = 0; k < 64; k++) {
        float xr[4], yc[4];
        #pragma unroll
        for (int r = 0; r < 4; r++) xr[r] = xsT[k * 65 + ty * 4 + r];
        #pragma unroll
        for (int c = 0; c < 4; c++) yc[c] = ysT[k * 65 + tx * 4 + c];
        #pragma unroll
        for (int r = 0; r < 4; r++)
            #pragma unroll
            for (int c = 0; c < 4; c++)
                acc[r][c] = fmaf(xr[r], yc[c], acc[r][c]);
    }
    __syncthreads();

    float xr2[4], yc2[4];
    #pragma unroll
    for (int r = 0; r < 4; r++) xr2[r] = x2s[ty * 4 + r];
    #pragma unroll
    for (int c = 0; c < 4; c++) yc2[c] = y2s[tx * 4 + c];
    #pragma unroll
    for (int r = 0; r < 4; r++)
        #pragma unroll
        for (int c = 0; c < 4; c++)
            res[ty * 4 + r][tx * 4 + c] =
                fmaxf(xr2[r] + yc2[c] - 2.0f * acc[r][c], 0.0f);
    __syncthreads();

    const int wid = tid >> 5, lane = tid & 31;
    const int dbase = br * 64 + bc * 64;
    for (int dl = wid; dl < 127; dl += 8) {
        int rlo = dl > 63 ? dl - 63 : 0;
        int rhi = dl < 63 ? dl : 63;
        size_t gbase = ((size_t)bz * NDIAG + (dbase + dl)) * TT + (size_t)br * 64;
        for (int r0 = rlo; r0 <= rhi; r0 += 32) {
            int r = r0 + lane;
            if (r <= rhi) g_cost[gbase + r] = res[r][dl - r];
        }
    }
}

__device__ __forceinline__ void bar_named(int id, int cnt) {
    asm volatile("bar.sync %0, %1;" :: "r"(id), "r"(cnt) : "memory");
}

// ---------------------------------------------------------------------------
// Kernel B: segment-pipelined anti-diagonal DP. 512 thr/CTA, 2 rows/thread.
// Information flows strictly low rows -> high rows, so warps form a
// producer-consumer pipeline. Neighbor sync happens once per SEG=8 diagonals
// (pairwise named barriers: gate on bar(w-1) before a segment, release on
// bar(w) after). Halo is a 32-deep ring (slot = k mod 32): producer lead is
// bounded by the release barrier at < 25 diagonals < 32, so no overwrite of
// unread slots. Inside a segment: pure register DP, 1 shfl + 1 STS + 1 LDS
// per diagonal, zero barriers. Costs prefetched one whole segment ahead
// (8 float2 loads batched, MLP=8). softmin = exp(0)=1 identity, 3 MUFU/cell.
// ---------------------------------------------------------------------------
#define SEG 8
#define NSEG 256   // SEG*NSEG = 2048 >= 2047 diagonals (k = 2..2048)

__global__ __launch_bounds__(512) void dp_kernel(float* __restrict__ out) {
    const int b = blockIdx.x;
    const int t = threadIdx.x;        // 0..511
    const int lane = t & 31;
    const int w = t >> 5;             // warp 0..15
    const int r0 = t << 1;            // owned rows r0, r0+1

    __shared__ float halo[32][16];    // [k mod 32][warp]

    float v1[2] = {BIGV, BIGV};       // d_{k-1}[r0+1], d_{k-1}[r0+2]
    float v2[2] = {BIGV, BIGV};       // d_{k-2}[...]
    float L1 = BIGV;                  // d_{k-1}[r0]
    float L2 = (t == 0) ? 0.0f : BIGV;// d_{k-2}[r0]  (d0[0] = 0)

    const float* costbase = g_cost + (size_t)b * NDIAG * TT + r0;
    const int kminA = r0 + 2;         // first diag with a valid cell here
    const int kmaxA = r0 + 2 + TT;    // last

    float res = BIGV;
    float2 cbuf[SEG], nbuf[SEG];

    // preload segment 0 costs (diags k = 2..9)
    #pragma unroll
    for (int j = 0; j < SEG; j++) {
        int k = 2 + j;
        cbuf[j] = make_float2(0.f, 0.f);
        if ((k >= kminA) & (k <= kmaxA))
            cbuf[j] = *(const float2*)(costbase + (size_t)(k - 2) * TT);
    }

    for (int s = 0; s < NSEG; s++) {
        // gate: left neighbor has finished producing this segment's halo values
        if (w > 0) bar_named(w - 1, 64);

        // batch-prefetch next segment's costs (consumed next iteration)
        #pragma unroll
        for (int j = 0; j < SEG; j++) {
            int k = SEG * (s + 1) + 2 + j;
            nbuf[j] = make_float2(0.f, 0.f);
            if ((k <= 2 * TT) & (k >= kminA) & (k <= kmaxA))
                nbuf[j] = *(const float2*)(costbase + (size_t)(k - 2) * TT);
        }

        #pragma unroll
        for (int j = 0; j < SEG; j++) {
            const int k = SEG * s + 2 + j;
            if (k > 2 * TT) break;

            const int rlo = k - 1 - TT;
            const int rhi = k - 2;

            float cur0, cur1;
            if ((k >= kminA) & (k <= kmaxA)) {
                {   // row r0+1 first (feeds shfl/halo)
                    float a  = v2[0];
                    float bb = v1[0];
                    float c  = v1[1];
                    float mnab = fminf(a, bb);
                    float mxab = fmaxf(a, bb);
                    float mn   = fminf(mnab, c);
                    float hi   = fmaxf(mxab, c);
                    float mid  = fmaxf(mnab, fminf(mxab, c));
                    float sum  = 1.0f + __expf(mn - mid) + __expf(mn - hi);
                    float sm   = mn - __logf(sum);
                    int r = r0 + 1;
                    cur1 = ((r >= rlo) & (r <= rhi)) ? cbuf[j].y + sm : BIGV;
                }
                {   // row r0
                    float a  = L2;
                    float bb = L1;
                    float c  = v1[0];
                    float mnab = fminf(a, bb);
                    float mxab = fmaxf(a, bb);
                    float mn   = fminf(mnab, c);
                    float hi   = fmaxf(mxab, c);
                    float mid  = fmaxf(mnab, fminf(mxab, c));
                    float sum  = 1.0f + __expf(mn - mid) + __expf(mn - hi);
                    float sm   = mn - __logf(sum);
                    cur0 = ((r0 >= rlo) & (r0 <= rhi)) ? cbuf[j].x + sm : BIGV;
                }
                res = cur1;
            } else {
                cur0 = BIGV; cur1 = BIGV;
            }

            // boundary handoff: d_k[r0] comes from left neighbor's cur1
            float nb = __shfl_up_sync(0xffffffffu, cur1, 1);
            if (lane == 31) halo[k & 31][w] = cur1;                 // produce
            if (lane == 0)  nb = (w == 0) ? BIGV : halo[k & 31][w - 1]; // consume (left warp is >= 1 segment ahead)

            L2 = L1;
            L1 = nb;
            v2[0] = v1[0]; v2[1] = v1[1];
            v1[0] = cur0;  v1[1] = cur1;
        }

        // release: right neighbor may now run this segment
        if (w < 15) bar_named(w, 64);

        #pragma unroll
        for (int j = 0; j < SEG; j++) cbuf[j] = nbuf[j];
    }

    // answer = d_{2T}[T]: DP idx 1024 = row 1023 = thread 511 row r0+1 (k=2048)
    if (t == 511) out[b] = res;
}

extern "C" void kernel_launch(void* const* d_in, const int* in_sizes, int n_in,
                              void* d_out, int out_size) {
    const float* x = (const float*)d_in[0];
    const float* y = (const float*)d_in[1];
    float* out = (float*)d_out;

    dim3 gridA(TT / 64, TT / 64, BB);   // (16, 16, 32)
    cost_kernel<<<gridA, 256>>>(x, y);
    dp_kernel<<<BB, 512>>>(out);
}

// round 9
// speedup vs baseline: 1.5139x; 1.0642x over previous
#include <cuda_runtime.h>

#define BIGV 1e10f
#define TT 1024
#define BB 32
#define DD 64
#define NDIAG 2047   // row+col in [0, 2046]

// Diagonal-major cost scratch: g_cost[b][d][row], d = row+col.
static __device__ float g_cost[(size_t)BB * NDIAG * TT];

// ---------------------------------------------------------------------------
// Kernel A: cost matrix (unchanged from round 1).
// ---------------------------------------------------------------------------
__global__ __launch_bounds__(256) void cost_kernel(const float* __restrict__ x,
                                                   const float* __restrict__ y) {
    const int bz = blockIdx.z;
    const int br = blockIdx.y;
    const int bc = blockIdx.x;
    const int tid = threadIdx.x;

    __shared__ float arena[2 * 64 * 65];
    __shared__ float x2s[64], y2s[64];
    float* xsT = arena;
    float* ysT = arena + 64 * 65;
    float (*res)[72] = (float (*)[72])arena;

    const float* xb = x + ((size_t)bz * TT + br * 64) * DD;
    const float* yb = y + ((size_t)bz * TT + bc * 64) * DD;

    #pragma unroll
    for (int i = 0; i < 16; i++) {
        int idx = tid + i * 256;
        int r = idx >> 6;
        int d = idx & 63;
        xsT[d * 65 + r] = xb[r * DD + d];
        ysT[d * 65 + r] = yb[r * DD + d];
    }
    __syncthreads();

    if (tid < 64) {
        float s = 0.f;
        #pragma unroll
        for (int k = 0; k < 64; k++) { float v = xsT[k * 65 + tid]; s = fmaf(v, v, s); }
        x2s[tid] = s;
    } else if (tid < 128) {
        int c = tid - 64;
        float s = 0.f;
        #pragma unroll
        for (int k = 0; k < 64; k++) { float v = ysT[k * 65 + c]; s = fmaf(v, v, s); }
        y2s[c] = s;
    }

    const int tx = tid & 15;
    const int ty = tid >> 4;
    float acc[4][4] = {};
    #pragma unroll
    for (int k = 0; k < 64; k++) {
        float xr[4], yc[4];
        #pragma unroll
        for (int r = 0; r < 4; r++) xr[r] = xsT[k * 65 + ty * 4 + r];
        #pragma unroll
        for (int c = 0; c < 4; c++) yc[c] = ysT[k * 65 + tx * 4 + c];
        #pragma unroll
        for (int r = 0; r < 4; r++)
            #pragma unroll
            for (int c = 0; c < 4; c++)
                acc[r][c] = fmaf(xr[r], yc[c], acc[r][c]);
    }
    __syncthreads();

    float xr2[4], yc2[4];
    #pragma unroll
    for (int r = 0; r < 4; r++) xr2[r] = x2s[ty * 4 + r];
    #pragma unroll
    for (int c = 0; c < 4; c++) yc2[c] = y2s[tx * 4 + c];
    #pragma unroll
    for (int r = 0; r < 4; r++)
        #pragma unroll
        for (int c = 0; c < 4; c++)
            res[ty * 4 + r][tx * 4 + c] =
                fmaxf(xr2[r] + yc2[c] - 2.0f * acc[r][c], 0.0f);
    __syncthreads();

    const int wid = tid >> 5, lane = tid & 31;
    const int dbase = br * 64 + bc * 64;
    for (int dl = wid; dl < 127; dl += 8) {
        int rlo = dl > 63 ? dl - 63 : 0;
        int rhi = dl < 63 ? dl : 63;
        size_t gbase = ((size_t)bz * NDIAG + (dbase + dl)) * TT + (size_t)br * 64;
        for (int r0 = rlo; r0 <= rhi; r0 += 32) {
            int r = r0 + lane;
            if (r <= rhi) g_cost[gbase + r] = res[r][dl - r];
        }
    }
}

__device__ __forceinline__ void bar_named(int id, int cnt) {
    asm volatile("bar.sync %0, %1;" :: "r"(id), "r"(cnt) : "memory");
}

__device__ __forceinline__ float softmin3(float a, float bb, float c) {
    float mnab = fminf(a, bb);
    float mxab = fmaxf(a, bb);
    float mn   = fminf(mnab, c);
    float hi   = fmaxf(mxab, c);
    float mid  = fmaxf(mnab, fminf(mxab, c));
    float sum  = 1.0f + __expf(mn - mid) + __expf(mn - hi);
    return mn - __logf(sum);
}

// ---------------------------------------------------------------------------
// Kernel B: segment-pipelined DP (round 6 structure) with warp-uniform
// segment specialization:
//  - inactive segments: one lane-parallel BIGV halo write, nothing else
//  - interior segments: unmasked fast path (no validity selects, raw loads)
//  - edge segments: the original masked slow path
// Pairwise named barriers per SEG=8 diagonals; 32-deep halo ring.
// ---------------------------------------------------------------------------
#define SEG 8
#define NSEG 256   // SEG*NSEG = 2048 >= 2047 diagonals (k = 2..2048)

__global__ __launch_bounds__(512) void dp_kernel(float* __restrict__ out) {
    const int b = blockIdx.x;
    const int t = threadIdx.x;        // 0..511
    const int lane = t & 31;
    const int w = t >> 5;             // warp 0..15
    const int r0 = t << 1;            // owned rows r0, r0+1

    __shared__ float halo[32][16];    // [k mod 32][warp]

    float v1[2] = {BIGV, BIGV};
    float v2[2] = {BIGV, BIGV};
    float L1 = BIGV;
    float L2 = (t == 0) ? 0.0f : BIGV;

    const float* costbase = g_cost + (size_t)b * NDIAG * TT + r0;
    const int kminA = r0 + 2;            // per-thread valid-k window
    const int kmaxA = r0 + 2 + TT;

    // warp-level windows (uniform across warp)
    const int W0 = 64 * w + 2;           // first diag any lane is valid
    const int W1 = 64 * w + 64 + TT;     // last diag any lane is valid
    const int F0 = 64 * w + 65;          // k >= F0: all 64 rows valid (rhi side)
    const int F1 = 64 * w + 1 + TT;      // k <= F1: all 64 rows valid (rlo side)
    const int P0 = 64 * w + 64;          // k >= P0: all lanes' loads in-window
    const int P1 = 64 * w + 2 + TT;      // k <= P1: all lanes' loads in-window

    float res = BIGV;
    float2 cbuf[SEG], nbuf[SEG];

    // preload segment 0 costs (masked)
    #pragma unroll
    for (int j = 0; j < SEG; j++) {
        int k = 2 + j;
        cbuf[j] = make_float2(0.f, 0.f);
        if ((k >= kminA) & (k <= kmaxA))
            cbuf[j] = *(const float2*)(costbase + (size_t)(k - 2) * TT);
    }

    int k0 = 2;
    for (int s = 0; s < NSEG; s++) {
        if (w > 0) bar_named(w - 1, 64);

        // ---- prefetch next segment ----
        const int k0n = k0 + SEG;
        if ((k0n <= W1) & (k0n + SEG - 1 >= W0) & (s + 1 < NSEG)) {
            const float* p = costbase + (size_t)(k0n - 2) * TT;
            if ((k0n >= P0) & (k0n + SEG - 1 <= P1)) {
                #pragma unroll
                for (int j = 0; j < SEG; j++)
                    nbuf[j] = *(const float2*)(p + (size_t)j * TT);
            } else {
                #pragma unroll
                for (int j = 0; j < SEG; j++) {
                    int k = k0n + j;
                    nbuf[j] = make_float2(0.f, 0.f);
                    if ((k >= kminA) & (k <= kmaxA))
                        nbuf[j] = *(const float2*)(p + (size_t)j * TT);
                }
            }
        }

        // ---- compute current segment ----
        if ((k0 > W1) | (k0 + SEG - 1 < W0)) {
            // inactive: publish BIGV halos for all 8 diagonals at once
            if (lane < SEG) halo[(k0 + lane) & 31][w] = BIGV;
        } else if ((k0 >= F0) & (k0 + SEG - 1 <= F1)) {
            // interior fast path: every cell valid, no masks
            #pragma unroll
            for (int j = 0; j < SEG; j++) {
                const int k = k0 + j;
                float cur1 = cbuf[j].y + softmin3(v2[0], v1[0], v1[1]);
                float cur0 = cbuf[j].x + softmin3(L2, L1, v1[0]);

                float nb = __shfl_up_sync(0xffffffffu, cur1, 1);
                if (lane == 31) halo[k & 31][w] = cur1;
                if (lane == 0)  nb = (w == 0) ? BIGV : halo[k & 31][w - 1];
                L2 = L1; L1 = nb;
                v2[0] = v1[0]; v2[1] = v1[1];
                v1[0] = cur0;  v1[1] = cur1;
                res = cur1;
            }
        } else {
            // edge slow path (masked)
            #pragma unroll
            for (int j = 0; j < SEG; j++) {
                const int k = k0 + j;
                const int rlo = k - 1 - TT;
                const int rhi = k - 2;

                float cur0, cur1;
                if ((k >= kminA) & (k <= kmaxA)) {
                    {
                        float sm = softmin3(v2[0], v1[0], v1[1]);
                        int r = r0 + 1;
                        cur1 = ((r >= rlo) & (r <= rhi)) ? cbuf[j].y + sm : BIGV;
                    }
                    {
                        float sm = softmin3(L2, L1, v1[0]);
                        cur0 = ((r0 >= rlo) & (r0 <= rhi)) ? cbuf[j].x + sm : BIGV;
                    }
                    res = cur1;
                } else {
                    cur0 = BIGV; cur1 = BIGV;
                }

                float nb = __shfl_up_sync(0xffffffffu, cur1, 1);
                if (lane == 31) halo[k & 31][w] = cur1;
                if (lane == 0)  nb = (w == 0) ? BIGV : halo[k & 31][w - 1];
                L2 = L1; L1 = nb;
                v2[0] = v1[0]; v2[1] = v1[1];
                v1[0] = cur0;  v1[1] = cur1;
            }
        }

        if (w < 15) bar_named(w, 64);

        #pragma unroll
        for (int j = 0; j < SEG; j++) cbuf[j] = nbuf[j];
        k0 = k0n;
    }

    // answer: row 1023 -> thread 511, second row (k = 2048)
    if (t == 511) out[b] = res;
}

extern "C" void kernel_launch(void* const* d_in, const int* in_sizes, int n_in,
                              void* d_out, int out_size) {
    const float* x = (const float*)d_in[0];
    const float* y = (const float*)d_in[1];
    float* out = (float*)d_out;

    dim3 gridA(TT / 64, TT / 64, BB);   // (16, 16, 32)
    cost_kernel<<<gridA, 256>>>(x, y);
    dp_kernel<<<BB, 512>>>(out);
}

// round 10
// speedup vs baseline: 1.5590x; 1.0298x over previous
#include <cuda_runtime.h>

#define BIGV 1e10f
#define TT 1024
#define BB 32
#define DD 64
#define NDIAG 2047   // row+col in [0, 2046]

// Diagonal-major cost scratch: g_cost[b][d][row], d = row+col.
static __device__ float g_cost[(size_t)BB * NDIAG * TT];

// ---------------------------------------------------------------------------
// Kernel A: cost matrix (unchanged from round 1).
// ---------------------------------------------------------------------------
__global__ __launch_bounds__(256) void cost_kernel(const float* __restrict__ x,
                                                   const float* __restrict__ y) {
    const int bz = blockIdx.z;
    const int br = blockIdx.y;
    const int bc = blockIdx.x;
    const int tid = threadIdx.x;

    __shared__ float arena[2 * 64 * 65];
    __shared__ float x2s[64], y2s[64];
    float* xsT = arena;
    float* ysT = arena + 64 * 65;
    float (*res)[72] = (float (*)[72])arena;

    const float* xb = x + ((size_t)bz * TT + br * 64) * DD;
    const float* yb = y + ((size_t)bz * TT + bc * 64) * DD;

    #pragma unroll
    for (int i = 0; i < 16; i++) {
        int idx = tid + i * 256;
        int r = idx >> 6;
        int d = idx & 63;
        xsT[d * 65 + r] = xb[r * DD + d];
        ysT[d * 65 + r] = yb[r * DD + d];
    }
    __syncthreads();

    if (tid < 64) {
        float s = 0.f;
        #pragma unroll
        for (int k = 0; k < 64; k++) { float v = xsT[k * 65 + tid]; s = fmaf(v, v, s); }
        x2s[tid] = s;
    } else if (tid < 128) {
        int c = tid - 64;
        float s = 0.f;
        #pragma unroll
        for (int k = 0; k < 64; k++) { float v = ysT[k * 65 + c]; s = fmaf(v, v, s); }
        y2s[c] = s;
    }

    const int tx = tid & 15;
    const int ty = tid >> 4;
    float acc[4][4] = {};
    #pragma unroll
    for (int k = 0; k < 64; k++) {
        float xr[4], yc[4];
        #pragma unroll
        for (int r = 0; r < 4; r++) xr[r] = xsT[k * 65 + ty * 4 + r];
        #pragma unroll
        for (int c = 0; c < 4; c++) yc[c] = ysT[k * 65 + tx * 4 + c];
        #pragma unroll
        for (int r = 0; r < 4; r++)
            #pragma unroll
            for (int c = 0; c < 4; c++)
                acc[r][c] = fmaf(xr[r], yc[c], acc[r][c]);
    }
    __syncthreads();

    float xr2[4], yc2[4];
    #pragma unroll
    for (int r = 0; r < 4; r++) xr2[r] = x2s[ty * 4 + r];
    #pragma unroll
    for (int c = 0; c < 4; c++) yc2[c] = y2s[tx * 4 + c];
    #pragma unroll
    for (int r = 0; r < 4; r++)
        #pragma unroll
        for (int c = 0; c < 4; c++)
            res[ty * 4 + r][tx * 4 + c] =
                fmaxf(xr2[r] + yc2[c] - 2.0f * acc[r][c], 0.0f);
    __syncthreads();

    const int wid = tid >> 5, lane = tid & 31;
    const int dbase = br * 64 + bc * 64;
    for (int dl = wid; dl < 127; dl += 8) {
        int rlo = dl > 63 ? dl - 63 : 0;
        int rhi = dl < 63 ? dl : 63;
        size_t gbase = ((size_t)bz * NDIAG + (dbase + dl)) * TT + (size_t)br * 64;
        for (int r0 = rlo; r0 <= rhi; r0 += 32) {
            int r = r0 + lane;
            if (r <= rhi) g_cost[gbase + r] = res[r][dl - r];
        }
    }
}

__device__ __forceinline__ float softmin3(float a, float bb, float c) {
    float mnab = fminf(a, bb);
    float mxab = fmaxf(a, bb);
    float mn   = fminf(mnab, c);
    float hi   = fmaxf(mxab, c);
    float mid  = fmaxf(mnab, fminf(mxab, c));
    float sum  = 1.0f + __expf(mn - mid) + __expf(mn - hi);
    return mn - __logf(sum);
}

// ---------------------------------------------------------------------------
// Kernel B: ELASTIC segment-pipelined DP. 512 thr/CTA, 2 rows/thread,
// SEG=8 diagonals per segment, 32-deep halo ring.
// Synchronization: per-warp monotonic progress counters in smem (no
// rendezvous barriers). Warp w waits for prog[w-1] >= s+1 (data ready) and
// prog[w+1] >= s-3 (halo-ring lead cap). Producers never block on consumers
// inside the slack window, so per-warp stalls stay local instead of
// convoying through all 16 warps. threadfence_block gives release/acquire
// ordering around the counter. Segment specialization from round 9 kept.
// ---------------------------------------------------------------------------
#define SEG 8
#define NSEG 256   // SEG*NSEG = 2048 >= 2047 diagonals (k = 2..2048)
#define LEADCAP 3

__global__ __launch_bounds__(512) void dp_kernel(float* __restrict__ out) {
    const int b = blockIdx.x;
    const int t = threadIdx.x;        // 0..511
    const int lane = t & 31;
    const int w = t >> 5;             // warp 0..15
    const int r0 = t << 1;            // owned rows r0, r0+1

    __shared__ float halo[32][16];    // [k mod 32][warp]
    __shared__ int prog[16];          // completed-segment counters

    if (t < 16) prog[t] = 0;
    __syncthreads();
    volatile int* vprog = prog;

    float v1[2] = {BIGV, BIGV};
    float v2[2] = {BIGV, BIGV};
    float L1 = BIGV;
    float L2 = (t == 0) ? 0.0f : BIGV;

    const float* costbase = g_cost + (size_t)b * NDIAG * TT + r0;
    const int kminA = r0 + 2;            // per-thread valid-k window
    const int kmaxA = r0 + 2 + TT;

    // warp-level windows (uniform across warp)
    const int W0 = 64 * w + 2;           // first diag any lane valid
    const int W1 = 64 * w + 64 + TT;     // last diag any lane valid
    const int F0 = 64 * w + 65;          // k >= F0: all 64 rows valid
    const int F1 = 64 * w + 1 + TT;      // k <= F1: all 64 rows valid
    const int P0 = 64 * w + 64;          // k >= P0: all lanes' loads in-window
    const int P1 = 64 * w + 2 + TT;      // k <= P1: all lanes' loads in-window

    float res = BIGV;
    float2 cbuf[SEG], nbuf[SEG];

    // preload segment 0 costs (masked)
    #pragma unroll
    for (int j = 0; j < SEG; j++) {
        int k = 2 + j;
        cbuf[j] = make_float2(0.f, 0.f);
        if ((k >= kminA) & (k <= kmaxA))
            cbuf[j] = *(const float2*)(costbase + (size_t)(k - 2) * TT);
    }

    int k0 = 2;
    for (int s = 0; s < NSEG; s++) {
        // gate: left neighbor finished segment s (halo values available)
        if (w > 0) {
            if (vprog[w - 1] < s + 1) {
                while (vprog[w - 1] < s + 1) __nanosleep(32);
            }
        }
        // lead cap: right neighbor within LEADCAP segments (halo ring safety)
        if (w < 15) {
            int tgt = s - LEADCAP;
            if (tgt > 0 && vprog[w + 1] < tgt) {
                while (vprog[w + 1] < tgt) __nanosleep(64);
            }
        }
        __threadfence_block();   // acquire: neighbor halo writes visible

        // ---- prefetch next segment ----
        const int k0n = k0 + SEG;
        if ((k0n <= W1) & (k0n + SEG - 1 >= W0) & (s + 1 < NSEG)) {
            const float* p = costbase + (size_t)(k0n - 2) * TT;
            if ((k0n >= P0) & (k0n + SEG - 1 <= P1)) {
                #pragma unroll
                for (int j = 0; j < SEG; j++)
                    nbuf[j] = *(const float2*)(p + (size_t)j * TT);
            } else {
                #pragma unroll
                for (int j = 0; j < SEG; j++) {
                    int k = k0n + j;
                    nbuf[j] = make_float2(0.f, 0.f);
                    if ((k >= kminA) & (k <= kmaxA))
                        nbuf[j] = *(const float2*)(p + (size_t)j * TT);
                }
            }
        }

        // ---- compute current segment ----
        if ((k0 > W1) | (k0 + SEG - 1 < W0)) {
            // inactive: publish BIGV halos for all 8 diagonals at once
            if (lane < SEG) halo[(k0 + lane) & 31][w] = BIGV;
        } else if ((k0 >= F0) & (k0 + SEG - 1 <= F1)) {
            // interior fast path: every cell valid, no masks
            #pragma unroll
            for (int j = 0; j < SEG; j++) {
                const int k = k0 + j;
                float cur1 = cbuf[j].y + softmin3(v2[0], v1[0], v1[1]);
                float cur0 = cbuf[j].x + softmin3(L2, L1, v1[0]);

                float nb = __shfl_up_sync(0xffffffffu, cur1, 1);
                if (lane == 31) halo[k & 31][w] = cur1;
                if (lane == 0)  nb = (w == 0) ? BIGV : halo[k & 31][w - 1];
                L2 = L1; L1 = nb;
                v2[0] = v1[0]; v2[1] = v1[1];
                v1[0] = cur0;  v1[1] = cur1;
                res = cur1;
            }
        } else {
            // edge slow path (masked)
            #pragma unroll
            for (int j = 0; j < SEG; j++) {
                const int k = k0 + j;
                const int rlo = k - 1 - TT;
                const int rhi = k - 2;

                float cur0, cur1;
                if ((k >= kminA) & (k <= kmaxA)) {
                    {
                        float sm = softmin3(v2[0], v1[0], v1[1]);
                        int r = r0 + 1;
                        cur1 = ((r >= rlo) & (r <= rhi)) ? cbuf[j].y + sm : BIGV;
                    }
                    {
                        float sm = softmin3(L2, L1, v1[0]);
                        cur0 = ((r0 >= rlo) & (r0 <= rhi)) ? cbuf[j].x + sm : BIGV;
                    }
                    res = cur1;
                } else {
                    cur0 = BIGV; cur1 = BIGV;
                }

                float nb = __shfl_up_sync(0xffffffffu, cur1, 1);
                if (lane == 31) halo[k & 31][w] = cur1;
                if (lane == 0)  nb = (w == 0) ? BIGV : halo[k & 31][w - 1];
                L2 = L1; L1 = nb;
                v2[0] = v1[0]; v2[1] = v1[1];
                v1[0] = cur0;  v1[1] = cur1;
            }
        }

        __threadfence_block();   // release: halo writes before counter bump
        if (lane == 0) vprog[w] = s + 1;

        #pragma unroll
        for (int j = 0; j < SEG; j++) cbuf[j] = nbuf[j];
        k0 = k0n;
    }

    // answer: row 1023 -> thread 511, second row (k = 2048)
    if (t == 511) out[b] = res;
}

extern "C" void kernel_launch(void* const* d_in, const int* in_sizes, int n_in,
                              void* d_out, int out_size) {
    const float* x = (const float*)d_in[0];
    const float* y = (const float*)d_in[1];
    float* out = (float*)d_out;

    dim3 gridA(TT / 64, TT / 64, BB);   // (16, 16, 32)
    cost_kernel<<<gridA, 256>>>(x, y);
    dp_kernel<<<BB, 512>>>(out);
}